// round 12
// baseline (speedup 1.0000x reference)
#include <cuda_runtime.h>
#include <cuda_fp16.h>
#include <cstdint>

#define HIDDEN 3072
#define NHEADS 24
#define HDIM   128
#define MLPH   12288
#define LSEQ   2048
#define N1     21504   // 3*HIDDEN + MLPH
#define NCAT   15360   // HIDDEN + MLPH
#define NMOD   9216

// ---------------- scratch (static device globals; no allocs) ----------------
__device__ float g_mod[NMOD];
__device__ __half g_xmodh[LSEQ * HIDDEN];
__device__ __half g_h[(size_t)LSEQ * NMOD];     // qkv (fp16)
__device__ uint32_t g_qh[LSEQ * (HIDDEN / 2)];
__device__ uint32_t g_kh[LSEQ * (HIDDEN / 2)];
__device__ __half g_a2h[(size_t)LSEQ * NCAT];
__device__ __half g_w1h[(size_t)HIDDEN * N1];
__device__ __half g_w2h[(size_t)NCAT * HIDDEN];

// ---------------- helpers ----------------
__device__ __forceinline__ uint32_t pk(float a, float b) {
    __half2 h = __floats2half2_rn(a, b);
    return *(uint32_t*)&h;
}

__device__ __forceinline__ void mma16(float* d, const uint32_t* a, const uint32_t* b) {
    asm volatile(
        "mma.sync.aligned.m16n8k16.row.col.f32.f16.f16.f32 "
        "{%0,%1,%2,%3}, {%4,%5,%6,%7}, {%8,%9}, {%0,%1,%2,%3};"
        : "+f"(d[0]), "+f"(d[1]), "+f"(d[2]), "+f"(d[3])
        : "r"(a[0]), "r"(a[1]), "r"(a[2]), "r"(a[3]), "r"(b[0]), "r"(b[1]));
}

__device__ __forceinline__ float gelu1(float x) {
    float x3 = x * x * x;
    return 0.5f * x * (1.f + tanhf(0.7978845608028654f * (x + 0.044715f * x3)));
}

__device__ __forceinline__ uint32_t smem_u32(const void* p) {
    uint32_t a;
    asm("{ .reg .u64 t; cvta.to.shared.u64 t, %1; cvt.u32.u64 %0, t; }" : "=r"(a) : "l"(p));
    return a;
}

#define CP16(dst, src) \
    asm volatile("cp.async.cg.shared.global [%0], [%1], 16;" :: "r"(dst), "l"(src))
#define CP_COMMIT() asm volatile("cp.async.commit_group;" ::: "memory")
#define CP_WAIT2()  asm volatile("cp.async.wait_group 2;" ::: "memory")
#define CP_WAIT1()  asm volatile("cp.async.wait_group 1;" ::: "memory")

#define LDM_X4(r0, r1, r2, r3, ad) \
    asm volatile("ldmatrix.sync.aligned.m8n8.x4.shared.b16 {%0,%1,%2,%3}, [%4];" \
                 : "=r"(r0), "=r"(r1), "=r"(r2), "=r"(r3) : "r"(ad))
#define LDM_X4T(r0, r1, r2, r3, ad) \
    asm volatile("ldmatrix.sync.aligned.m8n8.x4.trans.shared.b16 {%0,%1,%2,%3}, [%4];" \
                 : "=r"(r0), "=r"(r1), "=r"(r2), "=r"(r3) : "r"(ad))

// ---------------- 0+1) merged: w1 f32->f16 conversion ∥ mod GEMV ----------------
__global__ void __launch_bounds__(256) k_pre(const float* __restrict__ w1,
                                             __half* __restrict__ w1h,
                                             const float* __restrict__ vec,
                                             const float* __restrict__ W,
                                             const float* __restrict__ b) {
    if (blockIdx.x < 36) {  // mod = silu(vec) @ mod_w + mod_b
        __shared__ float sm[HIDDEN];
        for (int i = threadIdx.x; i < HIDDEN; i += 256) {
            float v = vec[i];
            sm[i] = v / (1.f + expf(-v));
        }
        __syncthreads();
        int j = blockIdx.x * 256 + threadIdx.x;
        float s0 = 0.f, s1 = 0.f, s2 = 0.f, s3 = 0.f;
        #pragma unroll 4
        for (int k = 0; k < HIDDEN; k += 4) {
            s0 = fmaf(sm[k + 0], W[(size_t)(k + 0) * NMOD + j], s0);
            s1 = fmaf(sm[k + 1], W[(size_t)(k + 1) * NMOD + j], s1);
            s2 = fmaf(sm[k + 2], W[(size_t)(k + 2) * NMOD + j], s2);
            s3 = fmaf(sm[k + 3], W[(size_t)(k + 3) * NMOD + j], s3);
        }
        g_mod[j] = (s0 + s1) + (s2 + s3) + b[j];
        return;
    }
    size_t i = ((size_t)(blockIdx.x - 36) * 256 + threadIdx.x) * 4;
    float4 v = *(const float4*)(w1 + i);
    *(uint32_t*)(w1h + i) = pk(v.x, v.y);
    *(uint32_t*)(w1h + i + 2) = pk(v.z, v.w);
}

// ---------------- 2) x_mod = (1+scale)*LN(x) + shift -> fp16 (one pass) --------
__global__ void __launch_bounds__(256) k_ln(const float* __restrict__ x) {
    int row = blockIdx.x;
    int tid = threadIdx.x;
    const float* xr = x + (size_t)row * HIDDEN;
    float2 xv[6];
    float s = 0.f, s2 = 0.f;
    #pragma unroll
    for (int i = 0; i < 6; i++) {
        xv[i] = *(const float2*)(xr + tid * 2 + i * 512);
        s += xv[i].x + xv[i].y;
        s2 = fmaf(xv[i].x, xv[i].x, fmaf(xv[i].y, xv[i].y, s2));
    }
    __shared__ float rs[8], rs2[8];
    for (int o = 16; o; o >>= 1) {
        s  += __shfl_xor_sync(~0u, s, o);
        s2 += __shfl_xor_sync(~0u, s2, o);
    }
    if ((tid & 31) == 0) { rs[tid >> 5] = s; rs2[tid >> 5] = s2; }
    __syncthreads();
    float ts = 0.f, ts2 = 0.f;
    #pragma unroll
    for (int i = 0; i < 8; i++) { ts += rs[i]; ts2 += rs2[i]; }
    float mu  = ts * (1.f / HIDDEN);
    float var = ts2 * (1.f / HIDDEN) - mu * mu;
    float rstd = rsqrtf(var + 1e-6f);
    #pragma unroll
    for (int i = 0; i < 6; i++) {
        int c = tid * 2 + i * 512;
        float v0 = (xv[i].x - mu) * rstd;
        float v1 = (xv[i].y - mu) * rstd;
        v0 = fmaf(g_mod[HIDDEN + c], v0, v0 + g_mod[c]);
        v1 = fmaf(g_mod[HIDDEN + c + 1], v1, v1 + g_mod[c + 1]);
        *(uint32_t*)&g_xmodh[(size_t)row * HIDDEN + c] = pk(v0, v1);
    }
}

// ---------------- 3/7) fp16 HMMA GEMM: 64x128, 3 CTA/SM, 5-stage, A-prefetch ----
// MODE 0: h = xmod @ w1 + b1; qkv -> g_h (fp16), mlp -> gelu -> g_a2h
// MODE 1: out = x + gate*(a2 @ w2 + b2)
template <int MODE>
__global__ void __launch_bounds__(128, 3)
gemm_cp(const __half* __restrict__ Bh, const float* __restrict__ bias,
        float* __restrict__ Cout, const float* __restrict__ xres) {
    constexpr int K = (MODE == 0) ? HIDDEN : NCAT;
    constexpr int N = (MODE == 0) ? N1 : HIDDEN;
    constexpr int Kt = K / 32;
    constexpr int STG = 13312;  // A 64*80 + B 32*256
    constexpr int NS = 5;

    extern __shared__ char smem[];
    const __half* Ah = (MODE == 0) ? g_xmodh : g_a2h;

    int tid = threadIdx.x;
    int bm = blockIdx.x, bn = blockIdx.y;
    int warp = tid >> 5, lane = tid & 31;
    int wm = warp & 1, wn = warp >> 1;
    int g = lane >> 2, tg = lane & 3;
    uint32_t sb = smem_u32(smem);

    auto issue = [&](int kt, int stage) {
        uint32_t sA = sb + stage * STG;
        uint32_t sB = sA + 5120;
        int kb = kt * 32;
        #pragma unroll
        for (int i = 0; i < 2; i++) {
            int op = tid + 128 * i;
            int arow = op >> 2, achk = op & 3;
            uint32_t dst = sA + arow * 80 + achk * 16;
            const __half* src = Ah + (size_t)(bm * 64 + arow) * K + kb + achk * 8;
            CP16(dst, src);
        }
        #pragma unroll
        for (int i = 0; i < 4; i++) {
            int op = tid + 128 * i;
            int krow = op >> 4, bchk = op & 15;
            uint32_t dst = sB + krow * 256 + ((bchk ^ (krow & 7)) << 4);
            const __half* src = Bh + (size_t)(kb + krow) * N + bn * 128 + bchk * 8;
            CP16(dst, src);
        }
        CP_COMMIT();
    };

    // A s=0 fragment addresses (stage-relative constants)
    uint32_t offA0[2];
    #pragma unroll
    for (int i = 0; i < 2; i++) {
        int row = wm * 32 + i * 16 + (lane & 7) + ((lane >> 3) & 1) * 8;
        offA0[i] = row * 80 + (lane >> 4) * 16;  // chunk = 0..1 for s=0
    }

    float acc[2][8][4];
    #pragma unroll
    for (int i = 0; i < 2; i++)
        #pragma unroll
        for (int j = 0; j < 8; j++)
            #pragma unroll
            for (int v = 0; v < 4; v++) acc[i][j][v] = 0.f;

    issue(0, 0);
    issue(1, 1);
    issue(2, 2);
    issue(3, 3);
    CP_WAIT2();           // tiles 0 and 1 ready
    __syncthreads();

    uint32_t afp[2][4];   // prefetched A s=0 fragments of the CURRENT tile
    LDM_X4(afp[0][0], afp[0][1], afp[0][2], afp[0][3], sb + offA0[0]);
    LDM_X4(afp[1][0], afp[1][1], afp[1][2], afp[1][3], sb + offA0[1]);

    int st = 0, stn = 4;
    for (int kt = 0; kt < Kt; kt++) {
        if (kt > 0) {
            CP_WAIT2();   // tiles kt and kt+1 guaranteed complete
            __syncthreads();
        }
        if (kt + 4 < Kt) issue(kt + 4, stn);
        else CP_COMMIT();

        uint32_t sA = sb + st * STG;
        uint32_t sB = sA + 5120;
        #pragma unroll
        for (int s = 0; s < 2; s++) {
            uint32_t af[2][4];
            if (s == 0) {
                #pragma unroll
                for (int i = 0; i < 2; i++)
                    #pragma unroll
                    for (int v = 0; v < 4; v++) af[i][v] = afp[i][v];
            } else {
                #pragma unroll
                for (int i = 0; i < 2; i++) {
                    int row = wm * 32 + i * 16 + (lane & 7) + ((lane >> 3) & 1) * 8;
                    int chunk = 2 + (lane >> 4);
                    uint32_t ad = sA + row * 80 + chunk * 16;
                    LDM_X4(af[i][0], af[i][1], af[i][2], af[i][3], ad);
                }
            }
            #pragma unroll
            for (int t = 0; t < 4; t++) {
                int j = 2 * t;
                int i2 = lane >> 3;
                int krow = s * 16 + (i2 & 1) * 8 + (lane & 7);
                int chunk = wn * 8 + j + (i2 >> 1);
                uint32_t ad = sB + krow * 256 + ((chunk ^ (krow & 7)) << 4);
                uint32_t b0, b1, b2, b3;
                LDM_X4T(b0, b1, b2, b3, ad);
                uint32_t bA[2] = {b0, b1}, bB[2] = {b2, b3};
                mma16(acc[0][j], af[0], bA);
                mma16(acc[1][j], af[1], bA);
                mma16(acc[0][j + 1], af[0], bB);
                mma16(acc[1][j + 1], af[1], bB);
            }
        }
        // prefetch next tile's s=0 A fragments (tile kt+1 ready; its stage is
        // not an overwrite target: issue writes stage (kt+4)%NS)
        if (kt + 1 < Kt) {
            uint32_t nb = sb + ((st + 1 == NS) ? 0 : st + 1) * STG;
            LDM_X4(afp[0][0], afp[0][1], afp[0][2], afp[0][3], nb + offA0[0]);
            LDM_X4(afp[1][0], afp[1][1], afp[1][2], afp[1][3], nb + offA0[1]);
        }
        if (++st == NS) st = 0;
        if (++stn == NS) stn = 0;
    }
    __syncthreads();

    // epilogue
    #pragma unroll
    for (int i = 0; i < 2; i++) {
        int r = bm * 64 + wm * 32 + i * 16 + g;
        #pragma unroll
        for (int j = 0; j < 8; j++) {
            int c = bn * 128 + wn * 64 + j * 8 + 2 * tg;
            float bb0 = bias[c], bb1 = bias[c + 1];
            float v00 = acc[i][j][0] + bb0, v01 = acc[i][j][1] + bb1;  // row r
            float v10 = acc[i][j][2] + bb0, v11 = acc[i][j][3] + bb1;  // row r+8
            if (MODE == 0) {
                if (bn < 72) {
                    *(uint32_t*)&g_h[(size_t)r * NMOD + c] = pk(v00, v01);
                    *(uint32_t*)&g_h[(size_t)(r + 8) * NMOD + c] = pk(v10, v11);
                } else {
                    int cc = c - NMOD + HIDDEN;
                    *(uint32_t*)&g_a2h[(size_t)r * NCAT + cc] = pk(gelu1(v00), gelu1(v01));
                    *(uint32_t*)&g_a2h[(size_t)(r + 8) * NCAT + cc] = pk(gelu1(v10), gelu1(v11));
                }
            } else {
                Cout[(size_t)r * HIDDEN + c] =
                    xres[(size_t)r * HIDDEN + c] + g_mod[2 * HIDDEN + c] * v00;
                Cout[(size_t)r * HIDDEN + c + 1] =
                    xres[(size_t)r * HIDDEN + c + 1] + g_mod[2 * HIDDEN + c + 1] * v01;
                Cout[(size_t)(r + 8) * HIDDEN + c] =
                    xres[(size_t)(r + 8) * HIDDEN + c] + g_mod[2 * HIDDEN + c] * v10;
                Cout[(size_t)(r + 8) * HIDDEN + c + 1] =
                    xres[(size_t)(r + 8) * HIDDEN + c + 1] + g_mod[2 * HIDDEN + c + 1] * v11;
            }
        }
    }
}

// ---------------- 4) per-head RMSNorm + RoPE -> packed half2 q/k ----------------
__global__ void __launch_bounds__(256) k_qkrope(const float* __restrict__ pe,
                                                const float* __restrict__ qw,
                                                const float* __restrict__ kw) {
    int l = blockIdx.x;
    int warp = threadIdx.x >> 5, lane = threadIdx.x & 31;
    const float sc = 0.08838834764831845f;  // 128^-0.5 folded into q
    #pragma unroll
    for (int hh = 0; hh < 3; hh++) {
        int h = warp * 3 + hh;
        #pragma unroll
        for (int qk = 0; qk < 2; qk++) {
            const __half* src = g_h + (size_t)l * NMOD + qk * HIDDEN + h * HDIM + lane * 4;
            const float* w = qk ? kw : qw;
            __half2 h0 = *(const __half2*)src;
            __half2 h1 = *(const __half2*)(src + 2);
            float2 va = __half22float2(h0);
            float2 vb = __half22float2(h1);
            float ss = va.x * va.x + va.y * va.y + vb.x * vb.x + vb.y * vb.y;
            for (int o = 16; o; o >>= 1) ss += __shfl_xor_sync(~0u, ss, o);
            float r = rsqrtf(ss * (1.f / HDIM) + 1e-6f);
            float4 w4 = *(const float4*)(w + lane * 4);
            float x0 = va.x * r * w4.x, x1 = va.y * r * w4.y;
            float x2 = vb.x * r * w4.z, x3 = vb.y * r * w4.w;
            const float* f = pe + (size_t)l * 256 + lane * 8;
            float mul = qk ? 1.f : sc;
            float o0 = (f[0] * x0 + f[1] * x1) * mul;
            float o1 = (f[2] * x0 + f[3] * x1) * mul;
            float o2 = (f[4] * x2 + f[5] * x3) * mul;
            float o3 = (f[6] * x2 + f[7] * x3) * mul;
            uint32_t* dst = (qk ? g_kh : g_qh) + (size_t)l * (HIDDEN / 2) + h * 64 + lane * 2;
            dst[0] = pk(o0, o1);
            dst[1] = pk(o2, o3);
        }
    }
}

// ---------------- 5) flash attention (x<32) + w2 fp16 conversion (x>=32) --------
__global__ void __launch_bounds__(128) k_attn(const float* __restrict__ w2,
                                              __half* __restrict__ w2h) {
    constexpr float SHIFT = 10.0f;
    __shared__ __align__(16) char sm[3 * 16384];  // per stage: K 8KB + V 8KB

    int tid = threadIdx.x;

    if (blockIdx.x >= 32) {  // w2 conversion blocks, interleaved with attn in x
        size_t blk = (size_t)blockIdx.y * 32 + (blockIdx.x - 32);  // 0..767
        size_t total = (size_t)NCAT * HIDDEN / 4;
        size_t stride = (size_t)768 * 128;
        for (size_t i = blk * 128 + tid; i < total; i += stride) {
            float4 v = *(const float4*)(w2 + i * 4);
            *(uint32_t*)(w2h + i * 4) = pk(v.x, v.y);
            *(uint32_t*)(w2h + i * 4 + 2) = pk(v.z, v.w);
        }
        return;
    }

    int h = blockIdx.y;
    int q0 = blockIdx.x * 64;
    int warp = tid >> 5, lane = tid & 31;
    int g = lane >> 2, tg = lane & 3;
    uint32_t sbase = smem_u32(sm);

    auto stage = [&](int t, int s) {
        int kv0 = t * 32;
        uint32_t base = sbase + s * 16384;
        #pragma unroll
        for (int i = 0; i < 4; i++) {
            int op = i * 128 + tid;
            int r = op >> 4, c = op & 15;
            uint32_t dst = base + r * 256 + ((c ^ (r & 7)) << 4);
            const char* src = (const char*)g_kh + (size_t)(kv0 + r) * (HIDDEN * 2) + h * 256 + c * 16;
            CP16(dst, src);
        }
        #pragma unroll
        for (int i = 0; i < 4; i++) {
            int op = i * 128 + tid;
            int r = op >> 4, c = op & 15;
            uint32_t dst = base + 8192 + r * 256 + ((c ^ (r & 7)) << 4);
            const char* src = (const char*)g_h + ((size_t)(kv0 + r) * NMOD + 2 * HIDDEN + h * HDIM) * 2 + c * 16;
            CP16(dst, src);
        }
        CP_COMMIT();
    };

    uint32_t qf[8][4];
    const uint32_t* qb = g_qh + (size_t)(q0 + warp * 16) * (HIDDEN / 2) + h * 64;
    #pragma unroll
    for (int ks = 0; ks < 8; ks++) {
        qf[ks][0] = qb[(size_t)g * (HIDDEN / 2) + ks * 8 + tg];
        qf[ks][1] = qb[(size_t)(g + 8) * (HIDDEN / 2) + ks * 8 + tg];
        qf[ks][2] = qb[(size_t)g * (HIDDEN / 2) + ks * 8 + tg + 4];
        qf[ks][3] = qb[(size_t)(g + 8) * (HIDDEN / 2) + ks * 8 + tg + 4];
    }

    float of[16][4];
    #pragma unroll
    for (int j = 0; j < 16; j++)
        #pragma unroll
        for (int v = 0; v < 4; v++) of[j][v] = 0.f;
    float l0 = 0.f, l1 = 0.f;

    stage(0, 0);
    stage(1, 1);

    for (int t = 0; t < LSEQ / 32; t++) {
        int st = t % 3;
        CP_WAIT1();
        __syncthreads();
        if (t + 2 < LSEQ / 32) stage(t + 2, (t + 2) % 3);
        else CP_COMMIT();

        uint32_t kbase = sbase + st * 16384;
        uint32_t vbase = kbase + 8192;

        float s_[4][4];
        #pragma unroll
        for (int j = 0; j < 4; j++)
            #pragma unroll
            for (int v = 0; v < 4; v++) s_[j][v] = 0.f;
        #pragma unroll
        for (int ks = 0; ks < 8; ks++) {
            #pragma unroll
            for (int hn = 0; hn < 2; hn++) {
                int r = hn * 16 + ((lane >> 4) << 3) + (lane & 7);
                int c = 2 * ks + ((lane >> 3) & 1);
                uint32_t ad = kbase + r * 256 + ((c ^ (r & 7)) << 4);
                uint32_t b0, b1, b2, b3;
                LDM_X4(b0, b1, b2, b3, ad);
                uint32_t bA[2] = {b0, b1}, bB[2] = {b2, b3};
                mma16(s_[2 * hn], qf[ks], bA);
                mma16(s_[2 * hn + 1], qf[ks], bB);
            }
        }

        #pragma unroll
        for (int j = 0; j < 4; j++) {
            s_[j][0] = __expf(s_[j][0] - SHIFT);
            s_[j][1] = __expf(s_[j][1] - SHIFT);
            s_[j][2] = __expf(s_[j][2] - SHIFT);
            s_[j][3] = __expf(s_[j][3] - SHIFT);
            l0 += s_[j][0] + s_[j][1];
            l1 += s_[j][2] + s_[j][3];
        }

        #pragma unroll
        for (int ks2 = 0; ks2 < 2; ks2++) {
            uint32_t af[4];
            af[0] = pk(s_[2 * ks2][0], s_[2 * ks2][1]);
            af[1] = pk(s_[2 * ks2][2], s_[2 * ks2][3]);
            af[2] = pk(s_[2 * ks2 + 1][0], s_[2 * ks2 + 1][1]);
            af[3] = pk(s_[2 * ks2 + 1][2], s_[2 * ks2 + 1][3]);
            #pragma unroll
            for (int tt = 0; tt < 8; tt++) {
                int r = ks2 * 16 + ((lane >> 3) & 1) * 8 + (lane & 7);
                int c = 2 * tt + (lane >> 4);
                uint32_t ad = vbase + r * 256 + ((c ^ (r & 7)) << 4);
                uint32_t b0, b1, b2, b3;
                LDM_X4T(b0, b1, b2, b3, ad);
                uint32_t bA[2] = {b0, b1}, bB[2] = {b2, b3};
                mma16(of[2 * tt], af, bA);
                mma16(of[2 * tt + 1], af, bB);
            }
        }
    }

    l0 += __shfl_xor_sync(~0u, l0, 1);
    l0 += __shfl_xor_sync(~0u, l0, 2);
    l1 += __shfl_xor_sync(~0u, l1, 1);
    l1 += __shfl_xor_sync(~0u, l1, 2);
    float il0 = 1.f / l0, il1 = 1.f / l1;
    int r0 = q0 + warp * 16 + g;
    int r1 = r0 + 8;
    #pragma unroll
    for (int j = 0; j < 16; j++) {
        int c = h * HDIM + j * 8 + 2 * tg;
        *(uint32_t*)&g_a2h[(size_t)r0 * NCAT + c] = pk(of[j][0] * il0, of[j][1] * il0);
        *(uint32_t*)&g_a2h[(size_t)r1 * NCAT + c] = pk(of[j][2] * il1, of[j][3] * il1);
    }
}

// ---------------- launch ----------------
extern "C" void kernel_launch(void* const* d_in, const int* in_sizes, int n_in,
                              void* d_out, int out_size) {
    const float* x     = (const float*)d_in[0];
    const float* vec   = (const float*)d_in[1];
    const float* pe    = (const float*)d_in[2];
    const float* w1    = (const float*)d_in[3];
    const float* b1    = (const float*)d_in[4];
    const float* w2    = (const float*)d_in[5];
    const float* b2    = (const float*)d_in[6];
    const float* mod_w = (const float*)d_in[7];
    const float* mod_b = (const float*)d_in[8];
    const float* qw    = (const float*)d_in[9];
    const float* kw    = (const float*)d_in[10];
    float* out = (float*)d_out;

    __half* w1h;  cudaGetSymbolAddress((void**)&w1h, g_w1h);
    __half* w2h;  cudaGetSymbolAddress((void**)&w2h, g_w2h);

    cudaFuncSetAttribute(gemm_cp<0>, cudaFuncAttributeMaxDynamicSharedMemorySize, 5 * 13312);
    cudaFuncSetAttribute(gemm_cp<1>, cudaFuncAttributeMaxDynamicSharedMemorySize, 5 * 13312);

    k_pre<<<36 + (HIDDEN * (N1 / 4)) / 256, 256>>>(w1, w1h, vec, mod_w, mod_b);
    k_ln<<<LSEQ, 256>>>(x);
    gemm_cp<0><<<dim3(32, 168), 128, 5 * 13312>>>(w1h, b1, nullptr, nullptr);
    k_qkrope<<<LSEQ, 256>>>(pe, qw, kw);
    k_attn<<<dim3(64, 24), 128>>>(w2, w2h);
    gemm_cp<1><<<dim3(32, 24), 128, 5 * 13312>>>(w2h, b2, out, x);
}

// round 13
// speedup vs baseline: 1.0070x; 1.0070x over previous
#include <cuda_runtime.h>
#include <cuda_fp16.h>
#include <cstdint>

#define HIDDEN 3072
#define NHEADS 24
#define HDIM   128
#define MLPH   12288
#define LSEQ   2048
#define N1     21504   // 3*HIDDEN + MLPH
#define NCAT   15360   // HIDDEN + MLPH
#define NMOD   9216

// ---------------- scratch (static device globals; no allocs) ----------------
__device__ float g_mod[NMOD];
__device__ __half g_xmodh[LSEQ * HIDDEN];
__device__ __half g_h[(size_t)LSEQ * NMOD];     // qkv (fp16)
__device__ uint32_t g_qh[LSEQ * (HIDDEN / 2)];
__device__ uint32_t g_kh[LSEQ * (HIDDEN / 2)];
__device__ __half g_a2h[(size_t)LSEQ * NCAT];
__device__ __half g_w1h[(size_t)HIDDEN * N1];
__device__ __half g_w2h[(size_t)NCAT * HIDDEN];

// ---------------- helpers ----------------
__device__ __forceinline__ uint32_t pk(float a, float b) {
    __half2 h = __floats2half2_rn(a, b);
    return *(uint32_t*)&h;
}

__device__ __forceinline__ void mma16(float* d, const uint32_t* a, const uint32_t* b) {
    asm volatile(
        "mma.sync.aligned.m16n8k16.row.col.f32.f16.f16.f32 "
        "{%0,%1,%2,%3}, {%4,%5,%6,%7}, {%8,%9}, {%0,%1,%2,%3};"
        : "+f"(d[0]), "+f"(d[1]), "+f"(d[2]), "+f"(d[3])
        : "r"(a[0]), "r"(a[1]), "r"(a[2]), "r"(a[3]), "r"(b[0]), "r"(b[1]));
}

__device__ __forceinline__ float gelu1(float x) {
    float x3 = x * x * x;
    return 0.5f * x * (1.f + tanhf(0.7978845608028654f * (x + 0.044715f * x3)));
}

__device__ __forceinline__ uint32_t smem_u32(const void* p) {
    uint32_t a;
    asm("{ .reg .u64 t; cvta.to.shared.u64 t, %1; cvt.u32.u64 %0, t; }" : "=r"(a) : "l"(p));
    return a;
}

#define CP16(dst, src) \
    asm volatile("cp.async.cg.shared.global [%0], [%1], 16;" :: "r"(dst), "l"(src))
#define CP_COMMIT() asm volatile("cp.async.commit_group;" ::: "memory")
#define CP_WAIT2()  asm volatile("cp.async.wait_group 2;" ::: "memory")
#define CP_WAIT1()  asm volatile("cp.async.wait_group 1;" ::: "memory")

#define LDM_X4(r0, r1, r2, r3, ad) \
    asm volatile("ldmatrix.sync.aligned.m8n8.x4.shared.b16 {%0,%1,%2,%3}, [%4];" \
                 : "=r"(r0), "=r"(r1), "=r"(r2), "=r"(r3) : "r"(ad))
#define LDM_X4T(r0, r1, r2, r3, ad) \
    asm volatile("ldmatrix.sync.aligned.m8n8.x4.trans.shared.b16 {%0,%1,%2,%3}, [%4];" \
                 : "=r"(r0), "=r"(r1), "=r"(r2), "=r"(r3) : "r"(ad))

// ---------------- 0+1) merged: w1 f32->f16 conversion ∥ mod GEMV ----------------
__global__ void __launch_bounds__(256) k_pre(const float* __restrict__ w1,
                                             __half* __restrict__ w1h,
                                             const float* __restrict__ vec,
                                             const float* __restrict__ W,
                                             const float* __restrict__ b) {
    if (blockIdx.x < 36) {  // mod = silu(vec) @ mod_w + mod_b
        __shared__ float sm[HIDDEN];
        for (int i = threadIdx.x; i < HIDDEN; i += 256) {
            float v = vec[i];
            sm[i] = v / (1.f + expf(-v));
        }
        __syncthreads();
        int j = blockIdx.x * 256 + threadIdx.x;
        float s0 = 0.f, s1 = 0.f, s2 = 0.f, s3 = 0.f;
        #pragma unroll 4
        for (int k = 0; k < HIDDEN; k += 4) {
            s0 = fmaf(sm[k + 0], W[(size_t)(k + 0) * NMOD + j], s0);
            s1 = fmaf(sm[k + 1], W[(size_t)(k + 1) * NMOD + j], s1);
            s2 = fmaf(sm[k + 2], W[(size_t)(k + 2) * NMOD + j], s2);
            s3 = fmaf(sm[k + 3], W[(size_t)(k + 3) * NMOD + j], s3);
        }
        g_mod[j] = (s0 + s1) + (s2 + s3) + b[j];
        return;
    }
    size_t i = ((size_t)(blockIdx.x - 36) * 256 + threadIdx.x) * 4;
    float4 v = *(const float4*)(w1 + i);
    *(uint32_t*)(w1h + i) = pk(v.x, v.y);
    *(uint32_t*)(w1h + i + 2) = pk(v.z, v.w);
}

// ---------------- 2) x_mod = (1+scale)*LN(x) + shift -> fp16 (one pass) --------
__global__ void __launch_bounds__(256) k_ln(const float* __restrict__ x) {
    int row = blockIdx.x;
    int tid = threadIdx.x;
    const float* xr = x + (size_t)row * HIDDEN;
    float2 xv[6];
    float s = 0.f, s2 = 0.f;
    #pragma unroll
    for (int i = 0; i < 6; i++) {
        xv[i] = *(const float2*)(xr + tid * 2 + i * 512);
        s += xv[i].x + xv[i].y;
        s2 = fmaf(xv[i].x, xv[i].x, fmaf(xv[i].y, xv[i].y, s2));
    }
    __shared__ float rs[8], rs2[8];
    for (int o = 16; o; o >>= 1) {
        s  += __shfl_xor_sync(~0u, s, o);
        s2 += __shfl_xor_sync(~0u, s2, o);
    }
    if ((tid & 31) == 0) { rs[tid >> 5] = s; rs2[tid >> 5] = s2; }
    __syncthreads();
    float ts = 0.f, ts2 = 0.f;
    #pragma unroll
    for (int i = 0; i < 8; i++) { ts += rs[i]; ts2 += rs2[i]; }
    float mu  = ts * (1.f / HIDDEN);
    float var = ts2 * (1.f / HIDDEN) - mu * mu;
    float rstd = rsqrtf(var + 1e-6f);
    #pragma unroll
    for (int i = 0; i < 6; i++) {
        int c = tid * 2 + i * 512;
        float v0 = (xv[i].x - mu) * rstd;
        float v1 = (xv[i].y - mu) * rstd;
        v0 = fmaf(g_mod[HIDDEN + c], v0, v0 + g_mod[c]);
        v1 = fmaf(g_mod[HIDDEN + c + 1], v1, v1 + g_mod[c + 1]);
        *(uint32_t*)&g_xmodh[(size_t)row * HIDDEN + c] = pk(v0, v1);
    }
}

// ---------------- 3/7) fp16 HMMA GEMM: 64x128, 3 CTA/SM, 5-stage, A-prefetch ----
// MODE 0: h = xmod @ w1 + b1; qkv -> g_h (fp16), mlp -> gelu -> g_a2h
// MODE 1: out = x + gate*(a2 @ w2 + b2)
template <int MODE>
__global__ void __launch_bounds__(128, 3)
gemm_cp(const __half* __restrict__ Bh, const float* __restrict__ bias,
        float* __restrict__ Cout, const float* __restrict__ xres) {
    constexpr int K = (MODE == 0) ? HIDDEN : NCAT;
    constexpr int N = (MODE == 0) ? N1 : HIDDEN;
    constexpr int Kt = K / 32;
    constexpr int STG = 13312;  // A 64*80 + B 32*256
    constexpr int NS = 5;

    extern __shared__ char smem[];
    const __half* Ah = (MODE == 0) ? g_xmodh : g_a2h;

    int tid = threadIdx.x;
    int bm = blockIdx.x, bn = blockIdx.y;
    int warp = tid >> 5, lane = tid & 31;
    int wm = warp & 1, wn = warp >> 1;
    int g = lane >> 2, tg = lane & 3;
    uint32_t sb = smem_u32(smem);

    auto issue = [&](int kt, int stage) {
        uint32_t sA = sb + stage * STG;
        uint32_t sB = sA + 5120;
        int kb = kt * 32;
        #pragma unroll
        for (int i = 0; i < 2; i++) {
            int op = tid + 128 * i;
            int arow = op >> 2, achk = op & 3;
            uint32_t dst = sA + arow * 80 + achk * 16;
            const __half* src = Ah + (size_t)(bm * 64 + arow) * K + kb + achk * 8;
            CP16(dst, src);
        }
        #pragma unroll
        for (int i = 0; i < 4; i++) {
            int op = tid + 128 * i;
            int krow = op >> 4, bchk = op & 15;
            uint32_t dst = sB + krow * 256 + ((bchk ^ (krow & 7)) << 4);
            const __half* src = Bh + (size_t)(kb + krow) * N + bn * 128 + bchk * 8;
            CP16(dst, src);
        }
        CP_COMMIT();
    };

    // A s=0 fragment addresses (stage-relative constants)
    uint32_t offA0[2];
    #pragma unroll
    for (int i = 0; i < 2; i++) {
        int row = wm * 32 + i * 16 + (lane & 7) + ((lane >> 3) & 1) * 8;
        offA0[i] = row * 80 + (lane >> 4) * 16;  // chunk = 0..1 for s=0
    }

    float acc[2][8][4];
    #pragma unroll
    for (int i = 0; i < 2; i++)
        #pragma unroll
        for (int j = 0; j < 8; j++)
            #pragma unroll
            for (int v = 0; v < 4; v++) acc[i][j][v] = 0.f;

    issue(0, 0);
    issue(1, 1);
    issue(2, 2);
    issue(3, 3);
    CP_WAIT2();           // tiles 0 and 1 ready
    __syncthreads();

    uint32_t afp[2][4];   // prefetched A s=0 fragments of the CURRENT tile
    LDM_X4(afp[0][0], afp[0][1], afp[0][2], afp[0][3], sb + offA0[0]);
    LDM_X4(afp[1][0], afp[1][1], afp[1][2], afp[1][3], sb + offA0[1]);

    int st = 0, stn = 4;
    for (int kt = 0; kt < Kt; kt++) {
        if (kt > 0) {
            CP_WAIT2();   // tiles kt and kt+1 guaranteed complete
            __syncthreads();
        }
        if (kt + 4 < Kt) issue(kt + 4, stn);
        else CP_COMMIT();

        uint32_t sA = sb + st * STG;
        uint32_t sB = sA + 5120;
        #pragma unroll
        for (int s = 0; s < 2; s++) {
            uint32_t af[2][4];
            if (s == 0) {
                #pragma unroll
                for (int i = 0; i < 2; i++)
                    #pragma unroll
                    for (int v = 0; v < 4; v++) af[i][v] = afp[i][v];
            } else {
                #pragma unroll
                for (int i = 0; i < 2; i++) {
                    int row = wm * 32 + i * 16 + (lane & 7) + ((lane >> 3) & 1) * 8;
                    int chunk = 2 + (lane >> 4);
                    uint32_t ad = sA + row * 80 + chunk * 16;
                    LDM_X4(af[i][0], af[i][1], af[i][2], af[i][3], ad);
                }
            }
            #pragma unroll
            for (int t = 0; t < 4; t++) {
                int j = 2 * t;
                int i2 = lane >> 3;
                int krow = s * 16 + (i2 & 1) * 8 + (lane & 7);
                int chunk = wn * 8 + j + (i2 >> 1);
                uint32_t ad = sB + krow * 256 + ((chunk ^ (krow & 7)) << 4);
                uint32_t b0, b1, b2, b3;
                LDM_X4T(b0, b1, b2, b3, ad);
                uint32_t bA[2] = {b0, b1}, bB[2] = {b2, b3};
                mma16(acc[0][j], af[0], bA);
                mma16(acc[1][j], af[1], bA);
                mma16(acc[0][j + 1], af[0], bB);
                mma16(acc[1][j + 1], af[1], bB);
            }
        }
        // prefetch next tile's s=0 A fragments (tile kt+1 ready; its stage is
        // not an overwrite target: issue writes stage (kt+4)%NS)
        if (kt + 1 < Kt) {
            uint32_t nb = sb + ((st + 1 == NS) ? 0 : st + 1) * STG;
            LDM_X4(afp[0][0], afp[0][1], afp[0][2], afp[0][3], nb + offA0[0]);
            LDM_X4(afp[1][0], afp[1][1], afp[1][2], afp[1][3], nb + offA0[1]);
        }
        if (++st == NS) st = 0;
        if (++stn == NS) stn = 0;
    }
    __syncthreads();

    // epilogue
    #pragma unroll
    for (int i = 0; i < 2; i++) {
        int r = bm * 64 + wm * 32 + i * 16 + g;
        #pragma unroll
        for (int j = 0; j < 8; j++) {
            int c = bn * 128 + wn * 64 + j * 8 + 2 * tg;
            float bb0 = bias[c], bb1 = bias[c + 1];
            float v00 = acc[i][j][0] + bb0, v01 = acc[i][j][1] + bb1;  // row r
            float v10 = acc[i][j][2] + bb0, v11 = acc[i][j][3] + bb1;  // row r+8
            if (MODE == 0) {
                if (bn < 72) {
                    *(uint32_t*)&g_h[(size_t)r * NMOD + c] = pk(v00, v01);
                    *(uint32_t*)&g_h[(size_t)(r + 8) * NMOD + c] = pk(v10, v11);
                } else {
                    int cc = c - NMOD + HIDDEN;
                    *(uint32_t*)&g_a2h[(size_t)r * NCAT + cc] = pk(gelu1(v00), gelu1(v01));
                    *(uint32_t*)&g_a2h[(size_t)(r + 8) * NCAT + cc] = pk(gelu1(v10), gelu1(v11));
                }
            } else {
                Cout[(size_t)r * HIDDEN + c] =
                    xres[(size_t)r * HIDDEN + c] + g_mod[2 * HIDDEN + c] * v00;
                Cout[(size_t)r * HIDDEN + c + 1] =
                    xres[(size_t)r * HIDDEN + c + 1] + g_mod[2 * HIDDEN + c + 1] * v01;
                Cout[(size_t)(r + 8) * HIDDEN + c] =
                    xres[(size_t)(r + 8) * HIDDEN + c] + g_mod[2 * HIDDEN + c] * v10;
                Cout[(size_t)(r + 8) * HIDDEN + c + 1] =
                    xres[(size_t)(r + 8) * HIDDEN + c + 1] + g_mod[2 * HIDDEN + c + 1] * v11;
            }
        }
    }
}

// ---------------- 4) per-head RMSNorm + RoPE -> packed half2 q/k ----------------
__global__ void __launch_bounds__(256) k_qkrope(const float* __restrict__ pe,
                                                const float* __restrict__ qw,
                                                const float* __restrict__ kw) {
    int l = blockIdx.x;
    int warp = threadIdx.x >> 5, lane = threadIdx.x & 31;
    const float sc = 0.08838834764831845f;  // 128^-0.5 folded into q
    #pragma unroll
    for (int hh = 0; hh < 3; hh++) {
        int h = warp * 3 + hh;
        #pragma unroll
        for (int qk = 0; qk < 2; qk++) {
            const __half* src = g_h + (size_t)l * NMOD + qk * HIDDEN + h * HDIM + lane * 4;
            const float* w = qk ? kw : qw;
            __half2 h0 = *(const __half2*)src;
            __half2 h1 = *(const __half2*)(src + 2);
            float2 va = __half22float2(h0);
            float2 vb = __half22float2(h1);
            float ss = va.x * va.x + va.y * va.y + vb.x * vb.x + vb.y * vb.y;
            for (int o = 16; o; o >>= 1) ss += __shfl_xor_sync(~0u, ss, o);
            float r = rsqrtf(ss * (1.f / HDIM) + 1e-6f);
            float4 w4 = *(const float4*)(w + lane * 4);
            float x0 = va.x * r * w4.x, x1 = va.y * r * w4.y;
            float x2 = vb.x * r * w4.z, x3 = vb.y * r * w4.w;
            const float* f = pe + (size_t)l * 256 + lane * 8;
            float mul = qk ? 1.f : sc;
            float o0 = (f[0] * x0 + f[1] * x1) * mul;
            float o1 = (f[2] * x0 + f[3] * x1) * mul;
            float o2 = (f[4] * x2 + f[5] * x3) * mul;
            float o3 = (f[6] * x2 + f[7] * x3) * mul;
            uint32_t* dst = (qk ? g_kh : g_qh) + (size_t)l * (HIDDEN / 2) + h * 64 + lane * 2;
            dst[0] = pk(o0, o1);
            dst[1] = pk(o2, o3);
        }
    }
}

// ---------------- 5) flash attention (x<32) + w2 fp16 conversion (x>=32) --------
__global__ void __launch_bounds__(128) k_attn(const float* __restrict__ w2,
                                              __half* __restrict__ w2h) {
    constexpr float SHIFT = 10.0f;
    __shared__ __align__(16) char sm[3 * 16384];  // per stage: K 8KB + V 8KB

    int tid = threadIdx.x;

    if (blockIdx.x >= 32) {  // w2 conversion blocks, interleaved with attn in x
        size_t blk = (size_t)blockIdx.y * 32 + (blockIdx.x - 32);  // 0..767
        size_t total = (size_t)NCAT * HIDDEN / 4;
        size_t stride = (size_t)768 * 128;
        for (size_t i = blk * 128 + tid; i < total; i += stride) {
            float4 v = *(const float4*)(w2 + i * 4);
            *(uint32_t*)(w2h + i * 4) = pk(v.x, v.y);
            *(uint32_t*)(w2h + i * 4 + 2) = pk(v.z, v.w);
        }
        return;
    }

    int h = blockIdx.y;
    int q0 = blockIdx.x * 64;
    int warp = tid >> 5, lane = tid & 31;
    int g = lane >> 2, tg = lane & 3;
    uint32_t sbase = smem_u32(sm);

    auto stage = [&](int t, int s) {
        int kv0 = t * 32;
        uint32_t base = sbase + s * 16384;
        #pragma unroll
        for (int i = 0; i < 4; i++) {
            int op = i * 128 + tid;
            int r = op >> 4, c = op & 15;
            uint32_t dst = base + r * 256 + ((c ^ (r & 7)) << 4);
            const char* src = (const char*)g_kh + (size_t)(kv0 + r) * (HIDDEN * 2) + h * 256 + c * 16;
            CP16(dst, src);
        }
        #pragma unroll
        for (int i = 0; i < 4; i++) {
            int op = i * 128 + tid;
            int r = op >> 4, c = op & 15;
            uint32_t dst = base + 8192 + r * 256 + ((c ^ (r & 7)) << 4);
            const char* src = (const char*)g_h + ((size_t)(kv0 + r) * NMOD + 2 * HIDDEN + h * HDIM) * 2 + c * 16;
            CP16(dst, src);
        }
        CP_COMMIT();
    };

    uint32_t qf[8][4];
    const uint32_t* qb = g_qh + (size_t)(q0 + warp * 16) * (HIDDEN / 2) + h * 64;
    #pragma unroll
    for (int ks = 0; ks < 8; ks++) {
        qf[ks][0] = qb[(size_t)g * (HIDDEN / 2) + ks * 8 + tg];
        qf[ks][1] = qb[(size_t)(g + 8) * (HIDDEN / 2) + ks * 8 + tg];
        qf[ks][2] = qb[(size_t)g * (HIDDEN / 2) + ks * 8 + tg + 4];
        qf[ks][3] = qb[(size_t)(g + 8) * (HIDDEN / 2) + ks * 8 + tg + 4];
    }

    float of[16][4];
    #pragma unroll
    for (int j = 0; j < 16; j++)
        #pragma unroll
        for (int v = 0; v < 4; v++) of[j][v] = 0.f;
    float l0 = 0.f, l1 = 0.f;

    stage(0, 0);
    stage(1, 1);

    for (int t = 0; t < LSEQ / 32; t++) {
        int st = t % 3;
        CP_WAIT1();
        __syncthreads();
        if (t + 2 < LSEQ / 32) stage(t + 2, (t + 2) % 3);
        else CP_COMMIT();

        uint32_t kbase = sbase + st * 16384;
        uint32_t vbase = kbase + 8192;

        float s_[4][4];
        #pragma unroll
        for (int j = 0; j < 4; j++)
            #pragma unroll
            for (int v = 0; v < 4; v++) s_[j][v] = 0.f;
        #pragma unroll
        for (int ks = 0; ks < 8; ks++) {
            #pragma unroll
            for (int hn = 0; hn < 2; hn++) {
                int r = hn * 16 + ((lane >> 4) << 3) + (lane & 7);
                int c = 2 * ks + ((lane >> 3) & 1);
                uint32_t ad = kbase + r * 256 + ((c ^ (r & 7)) << 4);
                uint32_t b0, b1, b2, b3;
                LDM_X4(b0, b1, b2, b3, ad);
                uint32_t bA[2] = {b0, b1}, bB[2] = {b2, b3};
                mma16(s_[2 * hn], qf[ks], bA);
                mma16(s_[2 * hn + 1], qf[ks], bB);
            }
        }

        #pragma unroll
        for (int j = 0; j < 4; j++) {
            s_[j][0] = __expf(s_[j][0] - SHIFT);
            s_[j][1] = __expf(s_[j][1] - SHIFT);
            s_[j][2] = __expf(s_[j][2] - SHIFT);
            s_[j][3] = __expf(s_[j][3] - SHIFT);
            l0 += s_[j][0] + s_[j][1];
            l1 += s_[j][2] + s_[j][3];
        }

        #pragma unroll
        for (int ks2 = 0; ks2 < 2; ks2++) {
            uint32_t af[4];
            af[0] = pk(s_[2 * ks2][0], s_[2 * ks2][1]);
            af[1] = pk(s_[2 * ks2][2], s_[2 * ks2][3]);
            af[2] = pk(s_[2 * ks2 + 1][0], s_[2 * ks2 + 1][1]);
            af[3] = pk(s_[2 * ks2 + 1][2], s_[2 * ks2 + 1][3]);
            #pragma unroll
            for (int tt = 0; tt < 8; tt++) {
                int r = ks2 * 16 + ((lane >> 3) & 1) * 8 + (lane & 7);
                int c = 2 * tt + (lane >> 4);
                uint32_t ad = vbase + r * 256 + ((c ^ (r & 7)) << 4);
                uint32_t b0, b1, b2, b3;
                LDM_X4T(b0, b1, b2, b3, ad);
                uint32_t bA[2] = {b0, b1}, bB[2] = {b2, b3};
                mma16(of[2 * tt], af, bA);
                mma16(of[2 * tt + 1], af, bB);
            }
        }
    }

    l0 += __shfl_xor_sync(~0u, l0, 1);
    l0 += __shfl_xor_sync(~0u, l0, 2);
    l1 += __shfl_xor_sync(~0u, l1, 1);
    l1 += __shfl_xor_sync(~0u, l1, 2);
    float il0 = 1.f / l0, il1 = 1.f / l1;
    int r0 = q0 + warp * 16 + g;
    int r1 = r0 + 8;
    #pragma unroll
    for (int j = 0; j < 16; j++) {
        int c = h * HDIM + j * 8 + 2 * tg;
        *(uint32_t*)&g_a2h[(size_t)r0 * NCAT + c] = pk(of[j][0] * il0, of[j][1] * il0);
        *(uint32_t*)&g_a2h[(size_t)r1 * NCAT + c] = pk(of[j][2] * il1, of[j][3] * il1);
    }
}

// ---------------- launch ----------------
extern "C" void kernel_launch(void* const* d_in, const int* in_sizes, int n_in,
                              void* d_out, int out_size) {
    const float* x     = (const float*)d_in[0];
    const float* vec   = (const float*)d_in[1];
    const float* pe    = (const float*)d_in[2];
    const float* w1    = (const float*)d_in[3];
    const float* b1    = (const float*)d_in[4];
    const float* w2    = (const float*)d_in[5];
    const float* b2    = (const float*)d_in[6];
    const float* mod_w = (const float*)d_in[7];
    const float* mod_b = (const float*)d_in[8];
    const float* qw    = (const float*)d_in[9];
    const float* kw    = (const float*)d_in[10];
    float* out = (float*)d_out;

    __half* w1h;  cudaGetSymbolAddress((void**)&w1h, g_w1h);
    __half* w2h;  cudaGetSymbolAddress((void**)&w2h, g_w2h);

    cudaFuncSetAttribute(gemm_cp<0>, cudaFuncAttributeMaxDynamicSharedMemorySize, 5 * 13312);
    cudaFuncSetAttribute(gemm_cp<1>, cudaFuncAttributeMaxDynamicSharedMemorySize, 5 * 13312);

    k_pre<<<36 + (HIDDEN * (N1 / 4)) / 256, 256>>>(w1, w1h, vec, mod_w, mod_b);
    k_ln<<<LSEQ, 256>>>(x);
    gemm_cp<0><<<dim3(32, 168), 128, 5 * 13312>>>(w1h, b1, nullptr, nullptr);
    k_qkrope<<<LSEQ, 256>>>(pe, qw, kw);
    k_attn<<<dim3(64, 24), 128>>>(w2, w2h);
    gemm_cp<1><<<dim3(32, 24), 128, 5 * 13312>>>(w2h, b2, out, x);
}

// round 14
// speedup vs baseline: 1.0807x; 1.0732x over previous
#include <cuda_runtime.h>
#include <cuda_fp16.h>
#include <cstdint>

#define HIDDEN 3072
#define NHEADS 24
#define HDIM   128
#define MLPH   12288
#define LSEQ   2048
#define N1     21504   // 3*HIDDEN + MLPH
#define NCAT   15360   // HIDDEN + MLPH
#define NMOD   9216

// ---------------- scratch (static device globals; no allocs) ----------------
__device__ float g_mod[NMOD];
__device__ __half g_xmodh[LSEQ * HIDDEN];
__device__ __half g_h[(size_t)LSEQ * NMOD];     // qkv (fp16)
__device__ uint32_t g_qh[LSEQ * (HIDDEN / 2)];
__device__ uint32_t g_kh[LSEQ * (HIDDEN / 2)];
__device__ __half g_a2h[(size_t)LSEQ * NCAT];
__device__ __half g_w1h[(size_t)HIDDEN * N1];
__device__ __half g_w2h[(size_t)NCAT * HIDDEN];

// ---------------- helpers ----------------
__device__ __forceinline__ uint32_t pk(float a, float b) {
    __half2 h = __floats2half2_rn(a, b);
    return *(uint32_t*)&h;
}

__device__ __forceinline__ void mma16(float* d, const uint32_t* a, const uint32_t* b) {
    asm volatile(
        "mma.sync.aligned.m16n8k16.row.col.f32.f16.f16.f32 "
        "{%0,%1,%2,%3}, {%4,%5,%6,%7}, {%8,%9}, {%0,%1,%2,%3};"
        : "+f"(d[0]), "+f"(d[1]), "+f"(d[2]), "+f"(d[3])
        : "r"(a[0]), "r"(a[1]), "r"(a[2]), "r"(a[3]), "r"(b[0]), "r"(b[1]));
}

__device__ __forceinline__ float gelu1(float x) {
    float x3 = x * x * x;
    return 0.5f * x * (1.f + tanhf(0.7978845608028654f * (x + 0.044715f * x3)));
}

__device__ __forceinline__ uint32_t smem_u32(const void* p) {
    uint32_t a;
    asm("{ .reg .u64 t; cvta.to.shared.u64 t, %1; cvt.u32.u64 %0, t; }" : "=r"(a) : "l"(p));
    return a;
}

#define CP16(dst, src) \
    asm volatile("cp.async.cg.shared.global [%0], [%1], 16;" :: "r"(dst), "l"(src))
#define CP_COMMIT() asm volatile("cp.async.commit_group;" ::: "memory")
#define CP_WAIT3()  asm volatile("cp.async.wait_group 3;" ::: "memory")
#define CP_WAIT1()  asm volatile("cp.async.wait_group 1;" ::: "memory")

#define LDM_X4(r0, r1, r2, r3, ad) \
    asm volatile("ldmatrix.sync.aligned.m8n8.x4.shared.b16 {%0,%1,%2,%3}, [%4];" \
                 : "=r"(r0), "=r"(r1), "=r"(r2), "=r"(r3) : "r"(ad))
#define LDM_X4T(r0, r1, r2, r3, ad) \
    asm volatile("ldmatrix.sync.aligned.m8n8.x4.trans.shared.b16 {%0,%1,%2,%3}, [%4];" \
                 : "=r"(r0), "=r"(r1), "=r"(r2), "=r"(r3) : "r"(ad))

// ---------------- 0+1) merged: w1 f32->f16 conversion ∥ mod GEMV ----------------
__global__ void __launch_bounds__(256) k_pre(const float* __restrict__ w1,
                                             __half* __restrict__ w1h,
                                             const float* __restrict__ vec,
                                             const float* __restrict__ W,
                                             const float* __restrict__ b) {
    if (blockIdx.x < 36) {  // mod = silu(vec) @ mod_w + mod_b
        __shared__ float sm[HIDDEN];
        for (int i = threadIdx.x; i < HIDDEN; i += 256) {
            float v = vec[i];
            sm[i] = v / (1.f + expf(-v));
        }
        __syncthreads();
        int j = blockIdx.x * 256 + threadIdx.x;
        float s0 = 0.f, s1 = 0.f, s2 = 0.f, s3 = 0.f;
        #pragma unroll 4
        for (int k = 0; k < HIDDEN; k += 4) {
            s0 = fmaf(sm[k + 0], W[(size_t)(k + 0) * NMOD + j], s0);
            s1 = fmaf(sm[k + 1], W[(size_t)(k + 1) * NMOD + j], s1);
            s2 = fmaf(sm[k + 2], W[(size_t)(k + 2) * NMOD + j], s2);
            s3 = fmaf(sm[k + 3], W[(size_t)(k + 3) * NMOD + j], s3);
        }
        g_mod[j] = (s0 + s1) + (s2 + s3) + b[j];
        return;
    }
    size_t i = ((size_t)(blockIdx.x - 36) * 256 + threadIdx.x) * 4;
    float4 v = *(const float4*)(w1 + i);
    *(uint32_t*)(w1h + i) = pk(v.x, v.y);
    *(uint32_t*)(w1h + i + 2) = pk(v.z, v.w);
}

// ---------------- 2) x_mod = (1+scale)*LN(x) + shift -> fp16 (one pass) --------
__global__ void __launch_bounds__(256) k_ln(const float* __restrict__ x) {
    int row = blockIdx.x;
    int tid = threadIdx.x;
    const float* xr = x + (size_t)row * HIDDEN;
    float2 xv[6];
    float s = 0.f, s2 = 0.f;
    #pragma unroll
    for (int i = 0; i < 6; i++) {
        xv[i] = *(const float2*)(xr + tid * 2 + i * 512);
        s += xv[i].x + xv[i].y;
        s2 = fmaf(xv[i].x, xv[i].x, fmaf(xv[i].y, xv[i].y, s2));
    }
    __shared__ float rs[8], rs2[8];
    for (int o = 16; o; o >>= 1) {
        s  += __shfl_xor_sync(~0u, s, o);
        s2 += __shfl_xor_sync(~0u, s2, o);
    }
    if ((tid & 31) == 0) { rs[tid >> 5] = s; rs2[tid >> 5] = s2; }
    __syncthreads();
    float ts = 0.f, ts2 = 0.f;
    #pragma unroll
    for (int i = 0; i < 8; i++) { ts += rs[i]; ts2 += rs2[i]; }
    float mu  = ts * (1.f / HIDDEN);
    float var = ts2 * (1.f / HIDDEN) - mu * mu;
    float rstd = rsqrtf(var + 1e-6f);
    #pragma unroll
    for (int i = 0; i < 6; i++) {
        int c = tid * 2 + i * 512;
        float v0 = (xv[i].x - mu) * rstd;
        float v1 = (xv[i].y - mu) * rstd;
        v0 = fmaf(g_mod[HIDDEN + c], v0, v0 + g_mod[c]);
        v1 = fmaf(g_mod[HIDDEN + c + 1], v1, v1 + g_mod[c + 1]);
        *(uint32_t*)&g_xmodh[(size_t)row * HIDDEN + c] = pk(v0, v1);
    }
}

// ---------------- 3/7) fp16 HMMA GEMM: 64x128 tile, 128 thr, 3 CTA/SM, 5-stage ----
// MODE 0: h = xmod @ w1 + b1; qkv -> g_h (fp16), mlp -> gelu -> g_a2h
// MODE 1: out = x + gate*(a2 @ w2 + b2)
template <int MODE>
__global__ void __launch_bounds__(128, 3)
gemm_cp(const __half* __restrict__ Bh, const float* __restrict__ bias,
        float* __restrict__ Cout, const float* __restrict__ xres) {
    constexpr int K = (MODE == 0) ? HIDDEN : NCAT;
    constexpr int N = (MODE == 0) ? N1 : HIDDEN;
    constexpr int Kt = K / 32;
    constexpr int STG = 13312;  // A 64*80 + B 32*256
    constexpr int NS = 5;

    extern __shared__ char smem[];
    const __half* Ah = (MODE == 0) ? g_xmodh : g_a2h;

    int tid = threadIdx.x;
    int bm = blockIdx.x, bn = blockIdx.y;
    int warp = tid >> 5, lane = tid & 31;
    int wm = warp & 1, wn = warp >> 1;
    int g = lane >> 2, tg = lane & 3;
    uint32_t sb = smem_u32(smem);

    auto issue = [&](int kt, int stage) {
        uint32_t sA = sb + stage * STG;
        uint32_t sB = sA + 5120;
        int kb = kt * 32;
        #pragma unroll
        for (int i = 0; i < 2; i++) {
            int op = tid + 128 * i;
            int arow = op >> 2, achk = op & 3;
            uint32_t dst = sA + arow * 80 + achk * 16;
            const __half* src = Ah + (size_t)(bm * 64 + arow) * K + kb + achk * 8;
            CP16(dst, src);
        }
        #pragma unroll
        for (int i = 0; i < 4; i++) {
            int op = tid + 128 * i;
            int krow = op >> 4, bchk = op & 15;
            uint32_t dst = sB + krow * 256 + ((bchk ^ (krow & 7)) << 4);
            const __half* src = Bh + (size_t)(kb + krow) * N + bn * 128 + bchk * 8;
            CP16(dst, src);
        }
        CP_COMMIT();
    };

    float acc[2][8][4];
    #pragma unroll
    for (int i = 0; i < 2; i++)
        #pragma unroll
        for (int j = 0; j < 8; j++)
            #pragma unroll
            for (int v = 0; v < 4; v++) acc[i][j][v] = 0.f;

    issue(0, 0);
    issue(1, 1);
    issue(2, 2);
    issue(3, 3);

    int st = 0, stn = 4;  // current stage, next-issue stage
    for (int kt = 0; kt < Kt; kt++) {
        CP_WAIT3();
        __syncthreads();
        if (kt + 4 < Kt) issue(kt + 4, stn);
        else CP_COMMIT();

        uint32_t sA = sb + st * STG;
        uint32_t sB = sA + 5120;
        #pragma unroll
        for (int s = 0; s < 2; s++) {
            uint32_t af[2][4];
            #pragma unroll
            for (int i = 0; i < 2; i++) {
                int row = wm * 32 + i * 16 + (lane & 7) + ((lane >> 3) & 1) * 8;
                int chunk = 2 * s + (lane >> 4);
                uint32_t ad = sA + row * 80 + chunk * 16;
                LDM_X4(af[i][0], af[i][1], af[i][2], af[i][3], ad);
            }
            #pragma unroll
            for (int t = 0; t < 4; t++) {
                int j = 2 * t;
                int i2 = lane >> 3;
                int krow = s * 16 + (i2 & 1) * 8 + (lane & 7);
                int chunk = wn * 8 + j + (i2 >> 1);
                uint32_t ad = sB + krow * 256 + ((chunk ^ (krow & 7)) << 4);
                uint32_t b0, b1, b2, b3;
                LDM_X4T(b0, b1, b2, b3, ad);
                uint32_t bA[2] = {b0, b1}, bB[2] = {b2, b3};
                mma16(acc[0][j], af[0], bA);
                mma16(acc[1][j], af[1], bA);
                mma16(acc[0][j + 1], af[0], bB);
                mma16(acc[1][j + 1], af[1], bB);
            }
        }
        if (++st == NS) st = 0;
        if (++stn == NS) stn = 0;
    }
    __syncthreads();

    // epilogue
    #pragma unroll
    for (int i = 0; i < 2; i++) {
        int r = bm * 64 + wm * 32 + i * 16 + g;
        #pragma unroll
        for (int j = 0; j < 8; j++) {
            int c = bn * 128 + wn * 64 + j * 8 + 2 * tg;
            float bb0 = bias[c], bb1 = bias[c + 1];
            float v00 = acc[i][j][0] + bb0, v01 = acc[i][j][1] + bb1;  // row r
            float v10 = acc[i][j][2] + bb0, v11 = acc[i][j][3] + bb1;  // row r+8
            if (MODE == 0) {
                if (bn < 72) {
                    *(uint32_t*)&g_h[(size_t)r * NMOD + c] = pk(v00, v01);
                    *(uint32_t*)&g_h[(size_t)(r + 8) * NMOD + c] = pk(v10, v11);
                } else {
                    int cc = c - NMOD + HIDDEN;
                    *(uint32_t*)&g_a2h[(size_t)r * NCAT + cc] = pk(gelu1(v00), gelu1(v01));
                    *(uint32_t*)&g_a2h[(size_t)(r + 8) * NCAT + cc] = pk(gelu1(v10), gelu1(v11));
                }
            } else {
                Cout[(size_t)r * HIDDEN + c] =
                    xres[(size_t)r * HIDDEN + c] + g_mod[2 * HIDDEN + c] * v00;
                Cout[(size_t)r * HIDDEN + c + 1] =
                    xres[(size_t)r * HIDDEN + c + 1] + g_mod[2 * HIDDEN + c + 1] * v01;
                Cout[(size_t)(r + 8) * HIDDEN + c] =
                    xres[(size_t)(r + 8) * HIDDEN + c] + g_mod[2 * HIDDEN + c] * v10;
                Cout[(size_t)(r + 8) * HIDDEN + c + 1] =
                    xres[(size_t)(r + 8) * HIDDEN + c + 1] + g_mod[2 * HIDDEN + c + 1] * v11;
            }
        }
    }
}

// ---------------- 4) per-head RMSNorm + RoPE -> packed half2 q/k ----------------
__global__ void __launch_bounds__(256) k_qkrope(const float* __restrict__ pe,
                                                const float* __restrict__ qw,
                                                const float* __restrict__ kw) {
    int l = blockIdx.x;
    int warp = threadIdx.x >> 5, lane = threadIdx.x & 31;
    const float sc = 0.08838834764831845f;  // 128^-0.5 folded into q
    #pragma unroll
    for (int hh = 0; hh < 3; hh++) {
        int h = warp * 3 + hh;
        #pragma unroll
        for (int qk = 0; qk < 2; qk++) {
            const __half* src = g_h + (size_t)l * NMOD + qk * HIDDEN + h * HDIM + lane * 4;
            const float* w = qk ? kw : qw;
            __half2 h0 = *(const __half2*)src;
            __half2 h1 = *(const __half2*)(src + 2);
            float2 va = __half22float2(h0);
            float2 vb = __half22float2(h1);
            float ss = va.x * va.x + va.y * va.y + vb.x * vb.x + vb.y * vb.y;
            for (int o = 16; o; o >>= 1) ss += __shfl_xor_sync(~0u, ss, o);
            float r = rsqrtf(ss * (1.f / HDIM) + 1e-6f);
            float4 w4 = *(const float4*)(w + lane * 4);
            float x0 = va.x * r * w4.x, x1 = va.y * r * w4.y;
            float x2 = vb.x * r * w4.z, x3 = vb.y * r * w4.w;
            const float* f = pe + (size_t)l * 256 + lane * 8;
            float mul = qk ? 1.f : sc;
            float o0 = (f[0] * x0 + f[1] * x1) * mul;
            float o1 = (f[2] * x0 + f[3] * x1) * mul;
            float o2 = (f[4] * x2 + f[5] * x3) * mul;
            float o3 = (f[6] * x2 + f[7] * x3) * mul;
            uint32_t* dst = (qk ? g_kh : g_qh) + (size_t)l * (HIDDEN / 2) + h * 64 + lane * 2;
            dst[0] = pk(o0, o1);
            dst[1] = pk(o2, o3);
        }
    }
}

// ---------------- 5) flash attention (x<32) + w2 fp16 conversion (x>=32) --------
__global__ void __launch_bounds__(128) k_attn(const float* __restrict__ w2,
                                              __half* __restrict__ w2h) {
    constexpr float SHIFT = 10.0f;
    __shared__ __align__(16) char sm[3 * 16384];  // per stage: K 8KB + V 8KB

    int tid = threadIdx.x;

    if (blockIdx.x >= 32) {  // w2 conversion blocks, interleaved with attn in x
        size_t blk = (size_t)blockIdx.y * 32 + (blockIdx.x - 32);  // 0..767
        size_t total = (size_t)NCAT * HIDDEN / 4;
        size_t stride = (size_t)768 * 128;
        for (size_t i = blk * 128 + tid; i < total; i += stride) {
            float4 v = *(const float4*)(w2 + i * 4);
            *(uint32_t*)(w2h + i * 4) = pk(v.x, v.y);
            *(uint32_t*)(w2h + i * 4 + 2) = pk(v.z, v.w);
        }
        return;
    }

    int h = blockIdx.y;
    int q0 = blockIdx.x * 64;
    int warp = tid >> 5, lane = tid & 31;
    int g = lane >> 2, tg = lane & 3;
    uint32_t sbase = smem_u32(sm);

    auto stage = [&](int t, int s) {
        int kv0 = t * 32;
        uint32_t base = sbase + s * 16384;
        #pragma unroll
        for (int i = 0; i < 4; i++) {
            int op = i * 128 + tid;
            int r = op >> 4, c = op & 15;
            uint32_t dst = base + r * 256 + ((c ^ (r & 7)) << 4);
            const char* src = (const char*)g_kh + (size_t)(kv0 + r) * (HIDDEN * 2) + h * 256 + c * 16;
            CP16(dst, src);
        }
        #pragma unroll
        for (int i = 0; i < 4; i++) {
            int op = i * 128 + tid;
            int r = op >> 4, c = op & 15;
            uint32_t dst = base + 8192 + r * 256 + ((c ^ (r & 7)) << 4);
            const char* src = (const char*)g_h + ((size_t)(kv0 + r) * NMOD + 2 * HIDDEN + h * HDIM) * 2 + c * 16;
            CP16(dst, src);
        }
        CP_COMMIT();
    };

    uint32_t qf[8][4];
    const uint32_t* qb = g_qh + (size_t)(q0 + warp * 16) * (HIDDEN / 2) + h * 64;
    #pragma unroll
    for (int ks = 0; ks < 8; ks++) {
        qf[ks][0] = qb[(size_t)g * (HIDDEN / 2) + ks * 8 + tg];
        qf[ks][1] = qb[(size_t)(g + 8) * (HIDDEN / 2) + ks * 8 + tg];
        qf[ks][2] = qb[(size_t)g * (HIDDEN / 2) + ks * 8 + tg + 4];
        qf[ks][3] = qb[(size_t)(g + 8) * (HIDDEN / 2) + ks * 8 + tg + 4];
    }

    float of[16][4];
    #pragma unroll
    for (int j = 0; j < 16; j++)
        #pragma unroll
        for (int v = 0; v < 4; v++) of[j][v] = 0.f;
    float l0 = 0.f, l1 = 0.f;

    stage(0, 0);
    stage(1, 1);

    for (int t = 0; t < LSEQ / 32; t++) {
        int st = t % 3;
        CP_WAIT1();
        __syncthreads();
        if (t + 2 < LSEQ / 32) stage(t + 2, (t + 2) % 3);
        else CP_COMMIT();

        uint32_t kbase = sbase + st * 16384;
        uint32_t vbase = kbase + 8192;

        float s_[4][4];
        #pragma unroll
        for (int j = 0; j < 4; j++)
            #pragma unroll
            for (int v = 0; v < 4; v++) s_[j][v] = 0.f;
        #pragma unroll
        for (int ks = 0; ks < 8; ks++) {
            #pragma unroll
            for (int hn = 0; hn < 2; hn++) {
                int r = hn * 16 + ((lane >> 4) << 3) + (lane & 7);
                int c = 2 * ks + ((lane >> 3) & 1);
                uint32_t ad = kbase + r * 256 + ((c ^ (r & 7)) << 4);
                uint32_t b0, b1, b2, b3;
                LDM_X4(b0, b1, b2, b3, ad);
                uint32_t bA[2] = {b0, b1}, bB[2] = {b2, b3};
                mma16(s_[2 * hn], qf[ks], bA);
                mma16(s_[2 * hn + 1], qf[ks], bB);
            }
        }

        #pragma unroll
        for (int j = 0; j < 4; j++) {
            s_[j][0] = __expf(s_[j][0] - SHIFT);
            s_[j][1] = __expf(s_[j][1] - SHIFT);
            s_[j][2] = __expf(s_[j][2] - SHIFT);
            s_[j][3] = __expf(s_[j][3] - SHIFT);
            l0 += s_[j][0] + s_[j][1];
            l1 += s_[j][2] + s_[j][3];
        }

        #pragma unroll
        for (int ks2 = 0; ks2 < 2; ks2++) {
            uint32_t af[4];
            af[0] = pk(s_[2 * ks2][0], s_[2 * ks2][1]);
            af[1] = pk(s_[2 * ks2][2], s_[2 * ks2][3]);
            af[2] = pk(s_[2 * ks2 + 1][0], s_[2 * ks2 + 1][1]);
            af[3] = pk(s_[2 * ks2 + 1][2], s_[2 * ks2 + 1][3]);
            #pragma unroll
            for (int tt = 0; tt < 8; tt++) {
                int r = ks2 * 16 + ((lane >> 3) & 1) * 8 + (lane & 7);
                int c = 2 * tt + (lane >> 4);
                uint32_t ad = vbase + r * 256 + ((c ^ (r & 7)) << 4);
                uint32_t b0, b1, b2, b3;
                LDM_X4T(b0, b1, b2, b3, ad);
                uint32_t bA[2] = {b0, b1}, bB[2] = {b2, b3};
                mma16(of[2 * tt], af, bA);
                mma16(of[2 * tt + 1], af, bB);
            }
        }
    }

    l0 += __shfl_xor_sync(~0u, l0, 1);
    l0 += __shfl_xor_sync(~0u, l0, 2);
    l1 += __shfl_xor_sync(~0u, l1, 1);
    l1 += __shfl_xor_sync(~0u, l1, 2);
    float il0 = 1.f / l0, il1 = 1.f / l1;
    int r0 = q0 + warp * 16 + g;
    int r1 = r0 + 8;
    #pragma unroll
    for (int j = 0; j < 16; j++) {
        int c = h * HDIM + j * 8 + 2 * tg;
        *(uint32_t*)&g_a2h[(size_t)r0 * NCAT + c] = pk(of[j][0] * il0, of[j][1] * il0);
        *(uint32_t*)&g_a2h[(size_t)r1 * NCAT + c] = pk(of[j][2] * il1, of[j][3] * il1);
    }
}

// ---------------- launch ----------------
extern "C" void kernel_launch(void* const* d_in, const int* in_sizes, int n_in,
                              void* d_out, int out_size) {
    const float* x     = (const float*)d_in[0];
    const float* vec   = (const float*)d_in[1];
    const float* pe    = (const float*)d_in[2];
    const float* w1    = (const float*)d_in[3];
    const float* b1    = (const float*)d_in[4];
    const float* w2    = (const float*)d_in[5];
    const float* b2    = (const float*)d_in[6];
    const float* mod_w = (const float*)d_in[7];
    const float* mod_b = (const float*)d_in[8];
    const float* qw    = (const float*)d_in[9];
    const float* kw    = (const float*)d_in[10];
    float* out = (float*)d_out;

    __half* w1h;  cudaGetSymbolAddress((void**)&w1h, g_w1h);
    __half* w2h;  cudaGetSymbolAddress((void**)&w2h, g_w2h);

    cudaFuncSetAttribute(gemm_cp<0>, cudaFuncAttributeMaxDynamicSharedMemorySize, 5 * 13312);
    cudaFuncSetAttribute(gemm_cp<1>, cudaFuncAttributeMaxDynamicSharedMemorySize, 5 * 13312);

    k_pre<<<36 + (HIDDEN * (N1 / 4)) / 256, 256>>>(w1, w1h, vec, mod_w, mod_b);
    k_ln<<<LSEQ, 256>>>(x);
    gemm_cp<0><<<dim3(32, 168), 128, 5 * 13312>>>(w1h, b1, nullptr, nullptr);
    k_qkrope<<<LSEQ, 256>>>(pe, qw, kw);
    k_attn<<<dim3(64, 24), 128>>>(w2, w2h);
    gemm_cp<1><<<dim3(32, 24), 128, 5 * 13312>>>(w2h, b2, out, x);
}

// round 15
// speedup vs baseline: 1.0817x; 1.0009x over previous
#include <cuda_runtime.h>
#include <cuda_fp16.h>
#include <cstdint>

#define HIDDEN 3072
#define NHEADS 24
#define HDIM   128
#define MLPH   12288
#define LSEQ   2048
#define N1     21504   // 3*HIDDEN + MLPH
#define NCAT   15360   // HIDDEN + MLPH
#define NMOD   9216

// ---------------- scratch (static device globals; no allocs) ----------------
__device__ float g_mod[NMOD];
__device__ __half g_xmodh[LSEQ * HIDDEN];
__device__ __half g_h[(size_t)LSEQ * NMOD];     // qkv (fp16)
__device__ uint32_t g_qh[LSEQ * (HIDDEN / 2)];
__device__ uint32_t g_kh[LSEQ * (HIDDEN / 2)];
__device__ __half g_a2h[(size_t)LSEQ * NCAT];
__device__ __half g_w1h[(size_t)HIDDEN * N1];
__device__ __half g_w2h[(size_t)NCAT * HIDDEN];

// ---------------- helpers ----------------
__device__ __forceinline__ uint32_t pk(float a, float b) {
    __half2 h = __floats2half2_rn(a, b);
    return *(uint32_t*)&h;
}

__device__ __forceinline__ void mma16(float* d, const uint32_t* a, const uint32_t* b) {
    asm volatile(
        "mma.sync.aligned.m16n8k16.row.col.f32.f16.f16.f32 "
        "{%0,%1,%2,%3}, {%4,%5,%6,%7}, {%8,%9}, {%0,%1,%2,%3};"
        : "+f"(d[0]), "+f"(d[1]), "+f"(d[2]), "+f"(d[3])
        : "r"(a[0]), "r"(a[1]), "r"(a[2]), "r"(a[3]), "r"(b[0]), "r"(b[1]));
}

__device__ __forceinline__ float gelu1(float x) {
    float x3 = x * x * x;
    return 0.5f * x * (1.f + tanhf(0.7978845608028654f * (x + 0.044715f * x3)));
}

__device__ __forceinline__ uint32_t smem_u32(const void* p) {
    uint32_t a;
    asm("{ .reg .u64 t; cvta.to.shared.u64 t, %1; cvt.u32.u64 %0, t; }" : "=r"(a) : "l"(p));
    return a;
}

#define CP16(dst, src) \
    asm volatile("cp.async.cg.shared.global [%0], [%1], 16;" :: "r"(dst), "l"(src))
#define CP_COMMIT() asm volatile("cp.async.commit_group;" ::: "memory")
#define CP_WAIT3()  asm volatile("cp.async.wait_group 3;" ::: "memory")
#define CP_WAIT1()  asm volatile("cp.async.wait_group 1;" ::: "memory")

#define LDM_X4(r0, r1, r2, r3, ad) \
    asm volatile("ldmatrix.sync.aligned.m8n8.x4.shared.b16 {%0,%1,%2,%3}, [%4];" \
                 : "=r"(r0), "=r"(r1), "=r"(r2), "=r"(r3) : "r"(ad))
#define LDM_X4T(r0, r1, r2, r3, ad) \
    asm volatile("ldmatrix.sync.aligned.m8n8.x4.trans.shared.b16 {%0,%1,%2,%3}, [%4];" \
                 : "=r"(r0), "=r"(r1), "=r"(r2), "=r"(r3) : "r"(ad))

// ---------------- 0+1) merged: w1 f32->f16 conversion ∥ mod GEMV ----------------
__global__ void __launch_bounds__(256) k_pre(const float* __restrict__ w1,
                                             __half* __restrict__ w1h,
                                             const float* __restrict__ vec,
                                             const float* __restrict__ W,
                                             const float* __restrict__ b) {
    if (blockIdx.x < 36) {  // mod = silu(vec) @ mod_w + mod_b
        __shared__ float sm[HIDDEN];
        for (int i = threadIdx.x; i < HIDDEN; i += 256) {
            float v = vec[i];
            sm[i] = v / (1.f + expf(-v));
        }
        __syncthreads();
        int j = blockIdx.x * 256 + threadIdx.x;
        float s0 = 0.f, s1 = 0.f, s2 = 0.f, s3 = 0.f;
        #pragma unroll 4
        for (int k = 0; k < HIDDEN; k += 4) {
            s0 = fmaf(sm[k + 0], W[(size_t)(k + 0) * NMOD + j], s0);
            s1 = fmaf(sm[k + 1], W[(size_t)(k + 1) * NMOD + j], s1);
            s2 = fmaf(sm[k + 2], W[(size_t)(k + 2) * NMOD + j], s2);
            s3 = fmaf(sm[k + 3], W[(size_t)(k + 3) * NMOD + j], s3);
        }
        g_mod[j] = (s0 + s1) + (s2 + s3) + b[j];
        return;
    }
    size_t i = ((size_t)(blockIdx.x - 36) * 256 + threadIdx.x) * 4;
    float4 v = *(const float4*)(w1 + i);
    *(uint32_t*)(w1h + i) = pk(v.x, v.y);
    *(uint32_t*)(w1h + i + 2) = pk(v.z, v.w);
}

// ---------------- 2) x_mod = (1+scale)*LN(x) + shift -> fp16 (one pass) --------
__global__ void __launch_bounds__(256) k_ln(const float* __restrict__ x) {
    int row = blockIdx.x;
    int tid = threadIdx.x;
    const float* xr = x + (size_t)row * HIDDEN;
    float2 xv[6];
    float s = 0.f, s2 = 0.f;
    #pragma unroll
    for (int i = 0; i < 6; i++) {
        xv[i] = *(const float2*)(xr + tid * 2 + i * 512);
        s += xv[i].x + xv[i].y;
        s2 = fmaf(xv[i].x, xv[i].x, fmaf(xv[i].y, xv[i].y, s2));
    }
    __shared__ float rs[8], rs2[8];
    for (int o = 16; o; o >>= 1) {
        s  += __shfl_xor_sync(~0u, s, o);
        s2 += __shfl_xor_sync(~0u, s2, o);
    }
    if ((tid & 31) == 0) { rs[tid >> 5] = s; rs2[tid >> 5] = s2; }
    __syncthreads();
    float ts = 0.f, ts2 = 0.f;
    #pragma unroll
    for (int i = 0; i < 8; i++) { ts += rs[i]; ts2 += rs2[i]; }
    float mu  = ts * (1.f / HIDDEN);
    float var = ts2 * (1.f / HIDDEN) - mu * mu;
    float rstd = rsqrtf(var + 1e-6f);
    #pragma unroll
    for (int i = 0; i < 6; i++) {
        int c = tid * 2 + i * 512;
        float v0 = (xv[i].x - mu) * rstd;
        float v1 = (xv[i].y - mu) * rstd;
        v0 = fmaf(g_mod[HIDDEN + c], v0, v0 + g_mod[c]);
        v1 = fmaf(g_mod[HIDDEN + c + 1], v1, v1 + g_mod[c + 1]);
        *(uint32_t*)&g_xmodh[(size_t)row * HIDDEN + c] = pk(v0, v1);
    }
}

// ---------------- 3/7) fp16 HMMA GEMM: 64x128 tile, 128 thr, 3 CTA/SM, 5-stage ----
// MODE 0: h = xmod @ w1 + b1; qkv -> g_h (fp16), mlp -> gelu -> g_a2h
// MODE 1: out = x + gate*(a2 @ w2 + b2)
template <int MODE>
__global__ void __launch_bounds__(128, 3)
gemm_cp(const __half* __restrict__ Bh, const float* __restrict__ bias,
        float* __restrict__ Cout, const float* __restrict__ xres) {
    constexpr int K = (MODE == 0) ? HIDDEN : NCAT;
    constexpr int N = (MODE == 0) ? N1 : HIDDEN;
    constexpr int Kt = K / 32;
    constexpr int STG = 13312;  // A 64*80 + B 32*256
    constexpr int NS = 5;

    extern __shared__ char smem[];
    const __half* Ah = (MODE == 0) ? g_xmodh : g_a2h;

    int tid = threadIdx.x;
    int bm = blockIdx.x, bn = blockIdx.y;
    int warp = tid >> 5, lane = tid & 31;
    int wm = warp & 1, wn = warp >> 1;
    int g = lane >> 2, tg = lane & 3;
    uint32_t sb = smem_u32(smem);

    auto issue = [&](int kt, int stage) {
        uint32_t sA = sb + stage * STG;
        uint32_t sB = sA + 5120;
        int kb = kt * 32;
        #pragma unroll
        for (int i = 0; i < 2; i++) {
            int op = tid + 128 * i;
            int arow = op >> 2, achk = op & 3;
            uint32_t dst = sA + arow * 80 + achk * 16;
            const __half* src = Ah + (size_t)(bm * 64 + arow) * K + kb + achk * 8;
            CP16(dst, src);
        }
        #pragma unroll
        for (int i = 0; i < 4; i++) {
            int op = tid + 128 * i;
            int krow = op >> 4, bchk = op & 15;
            uint32_t dst = sB + krow * 256 + ((bchk ^ (krow & 7)) << 4);
            const __half* src = Bh + (size_t)(kb + krow) * N + bn * 128 + bchk * 8;
            CP16(dst, src);
        }
        CP_COMMIT();
    };

    float acc[2][8][4];
    #pragma unroll
    for (int i = 0; i < 2; i++)
        #pragma unroll
        for (int j = 0; j < 8; j++)
            #pragma unroll
            for (int v = 0; v < 4; v++) acc[i][j][v] = 0.f;

    issue(0, 0);
    issue(1, 1);
    issue(2, 2);
    issue(3, 3);

    int st = 0, stn = 4;  // current stage, next-issue stage
    for (int kt = 0; kt < Kt; kt++) {
        CP_WAIT3();
        __syncthreads();
        if (kt + 4 < Kt) issue(kt + 4, stn);
        else CP_COMMIT();

        uint32_t sA = sb + st * STG;
        uint32_t sB = sA + 5120;
        #pragma unroll
        for (int s = 0; s < 2; s++) {
            uint32_t af[2][4];
            #pragma unroll
            for (int i = 0; i < 2; i++) {
                int row = wm * 32 + i * 16 + (lane & 7) + ((lane >> 3) & 1) * 8;
                int chunk = 2 * s + (lane >> 4);
                uint32_t ad = sA + row * 80 + chunk * 16;
                LDM_X4(af[i][0], af[i][1], af[i][2], af[i][3], ad);
            }
            #pragma unroll
            for (int t = 0; t < 4; t++) {
                int j = 2 * t;
                int i2 = lane >> 3;
                int krow = s * 16 + (i2 & 1) * 8 + (lane & 7);
                int chunk = wn * 8 + j + (i2 >> 1);
                uint32_t ad = sB + krow * 256 + ((chunk ^ (krow & 7)) << 4);
                uint32_t b0, b1, b2, b3;
                LDM_X4T(b0, b1, b2, b3, ad);
                uint32_t bA[2] = {b0, b1}, bB[2] = {b2, b3};
                mma16(acc[0][j], af[0], bA);
                mma16(acc[1][j], af[1], bA);
                mma16(acc[0][j + 1], af[0], bB);
                mma16(acc[1][j + 1], af[1], bB);
            }
        }
        if (++st == NS) st = 0;
        if (++stn == NS) stn = 0;
    }
    __syncthreads();

    // epilogue
    #pragma unroll
    for (int i = 0; i < 2; i++) {
        int r = bm * 64 + wm * 32 + i * 16 + g;
        #pragma unroll
        for (int j = 0; j < 8; j++) {
            int c = bn * 128 + wn * 64 + j * 8 + 2 * tg;
            float bb0 = bias[c], bb1 = bias[c + 1];
            float v00 = acc[i][j][0] + bb0, v01 = acc[i][j][1] + bb1;  // row r
            float v10 = acc[i][j][2] + bb0, v11 = acc[i][j][3] + bb1;  // row r+8
            if (MODE == 0) {
                if (bn < 72) {
                    *(uint32_t*)&g_h[(size_t)r * NMOD + c] = pk(v00, v01);
                    *(uint32_t*)&g_h[(size_t)(r + 8) * NMOD + c] = pk(v10, v11);
                } else {
                    int cc = c - NMOD + HIDDEN;
                    *(uint32_t*)&g_a2h[(size_t)r * NCAT + cc] = pk(gelu1(v00), gelu1(v01));
                    *(uint32_t*)&g_a2h[(size_t)(r + 8) * NCAT + cc] = pk(gelu1(v10), gelu1(v11));
                }
            } else {
                Cout[(size_t)r * HIDDEN + c] =
                    xres[(size_t)r * HIDDEN + c] + g_mod[2 * HIDDEN + c] * v00;
                Cout[(size_t)r * HIDDEN + c + 1] =
                    xres[(size_t)r * HIDDEN + c + 1] + g_mod[2 * HIDDEN + c + 1] * v01;
                Cout[(size_t)(r + 8) * HIDDEN + c] =
                    xres[(size_t)(r + 8) * HIDDEN + c] + g_mod[2 * HIDDEN + c] * v10;
                Cout[(size_t)(r + 8) * HIDDEN + c + 1] =
                    xres[(size_t)(r + 8) * HIDDEN + c + 1] + g_mod[2 * HIDDEN + c + 1] * v11;
            }
        }
    }
}

// ---------------- 4) per-head RMSNorm + RoPE -> packed half2 q/k ----------------
__global__ void __launch_bounds__(256) k_qkrope(const float* __restrict__ pe,
                                                const float* __restrict__ qw,
                                                const float* __restrict__ kw) {
    int l = blockIdx.x;
    int warp = threadIdx.x >> 5, lane = threadIdx.x & 31;
    const float sc = 0.08838834764831845f;  // 128^-0.5 folded into q
    #pragma unroll
    for (int hh = 0; hh < 3; hh++) {
        int h = warp * 3 + hh;
        #pragma unroll
        for (int qk = 0; qk < 2; qk++) {
            const __half* src = g_h + (size_t)l * NMOD + qk * HIDDEN + h * HDIM + lane * 4;
            const float* w = qk ? kw : qw;
            __half2 h0 = *(const __half2*)src;
            __half2 h1 = *(const __half2*)(src + 2);
            float2 va = __half22float2(h0);
            float2 vb = __half22float2(h1);
            float ss = va.x * va.x + va.y * va.y + vb.x * vb.x + vb.y * vb.y;
            for (int o = 16; o; o >>= 1) ss += __shfl_xor_sync(~0u, ss, o);
            float r = rsqrtf(ss * (1.f / HDIM) + 1e-6f);
            float4 w4 = *(const float4*)(w + lane * 4);
            float x0 = va.x * r * w4.x, x1 = va.y * r * w4.y;
            float x2 = vb.x * r * w4.z, x3 = vb.y * r * w4.w;
            const float* f = pe + (size_t)l * 256 + lane * 8;
            float mul = qk ? 1.f : sc;
            float o0 = (f[0] * x0 + f[1] * x1) * mul;
            float o1 = (f[2] * x0 + f[3] * x1) * mul;
            float o2 = (f[4] * x2 + f[5] * x3) * mul;
            float o3 = (f[6] * x2 + f[7] * x3) * mul;
            uint32_t* dst = (qk ? g_kh : g_qh) + (size_t)l * (HIDDEN / 2) + h * 64 + lane * 2;
            dst[0] = pk(o0, o1);
            dst[1] = pk(o2, o3);
        }
    }
}

// ---------------- 5) flash attention (x<32) + w2 fp16 conversion (x>=32) --------
__global__ void __launch_bounds__(128) k_attn(const float* __restrict__ w2,
                                              __half* __restrict__ w2h) {
    constexpr float SHIFT = 10.0f;
    __shared__ __align__(16) char sm[3 * 16384];  // per stage: K 8KB + V 8KB

    int tid = threadIdx.x;

    if (blockIdx.x >= 32) {  // w2 conversion blocks, interleaved with attn in x
        size_t blk = (size_t)blockIdx.y * 32 + (blockIdx.x - 32);  // 0..767
        size_t total = (size_t)NCAT * HIDDEN / 4;
        size_t stride = (size_t)768 * 128;
        for (size_t i = blk * 128 + tid; i < total; i += stride) {
            float4 v = *(const float4*)(w2 + i * 4);
            *(uint32_t*)(w2h + i * 4) = pk(v.x, v.y);
            *(uint32_t*)(w2h + i * 4 + 2) = pk(v.z, v.w);
        }
        return;
    }

    int h = blockIdx.y;
    int q0 = blockIdx.x * 64;
    int warp = tid >> 5, lane = tid & 31;
    int g = lane >> 2, tg = lane & 3;
    uint32_t sbase = smem_u32(sm);

    auto stage = [&](int t, int s) {
        int kv0 = t * 32;
        uint32_t base = sbase + s * 16384;
        #pragma unroll
        for (int i = 0; i < 4; i++) {
            int op = i * 128 + tid;
            int r = op >> 4, c = op & 15;
            uint32_t dst = base + r * 256 + ((c ^ (r & 7)) << 4);
            const char* src = (const char*)g_kh + (size_t)(kv0 + r) * (HIDDEN * 2) + h * 256 + c * 16;
            CP16(dst, src);
        }
        #pragma unroll
        for (int i = 0; i < 4; i++) {
            int op = i * 128 + tid;
            int r = op >> 4, c = op & 15;
            uint32_t dst = base + 8192 + r * 256 + ((c ^ (r & 7)) << 4);
            const char* src = (const char*)g_h + ((size_t)(kv0 + r) * NMOD + 2 * HIDDEN + h * HDIM) * 2 + c * 16;
            CP16(dst, src);
        }
        CP_COMMIT();
    };

    uint32_t qf[8][4];
    const uint32_t* qb = g_qh + (size_t)(q0 + warp * 16) * (HIDDEN / 2) + h * 64;
    #pragma unroll
    for (int ks = 0; ks < 8; ks++) {
        qf[ks][0] = qb[(size_t)g * (HIDDEN / 2) + ks * 8 + tg];
        qf[ks][1] = qb[(size_t)(g + 8) * (HIDDEN / 2) + ks * 8 + tg];
        qf[ks][2] = qb[(size_t)g * (HIDDEN / 2) + ks * 8 + tg + 4];
        qf[ks][3] = qb[(size_t)(g + 8) * (HIDDEN / 2) + ks * 8 + tg + 4];
    }

    float of[16][4];
    #pragma unroll
    for (int j = 0; j < 16; j++)
        #pragma unroll
        for (int v = 0; v < 4; v++) of[j][v] = 0.f;
    float l0 = 0.f, l1 = 0.f;

    stage(0, 0);
    stage(1, 1);

    for (int t = 0; t < LSEQ / 32; t++) {
        int st = t % 3;
        CP_WAIT1();
        __syncthreads();
        if (t + 2 < LSEQ / 32) stage(t + 2, (t + 2) % 3);
        else CP_COMMIT();

        uint32_t kbase = sbase + st * 16384;
        uint32_t vbase = kbase + 8192;

        float s_[4][4];
        #pragma unroll
        for (int j = 0; j < 4; j++)
            #pragma unroll
            for (int v = 0; v < 4; v++) s_[j][v] = 0.f;
        #pragma unroll
        for (int ks = 0; ks < 8; ks++) {
            #pragma unroll
            for (int hn = 0; hn < 2; hn++) {
                int r = hn * 16 + ((lane >> 4) << 3) + (lane & 7);
                int c = 2 * ks + ((lane >> 3) & 1);
                uint32_t ad = kbase + r * 256 + ((c ^ (r & 7)) << 4);
                uint32_t b0, b1, b2, b3;
                LDM_X4(b0, b1, b2, b3, ad);
                uint32_t bA[2] = {b0, b1}, bB[2] = {b2, b3};
                mma16(s_[2 * hn], qf[ks], bA);
                mma16(s_[2 * hn + 1], qf[ks], bB);
            }
        }

        #pragma unroll
        for (int j = 0; j < 4; j++) {
            s_[j][0] = __expf(s_[j][0] - SHIFT);
            s_[j][1] = __expf(s_[j][1] - SHIFT);
            s_[j][2] = __expf(s_[j][2] - SHIFT);
            s_[j][3] = __expf(s_[j][3] - SHIFT);
            l0 += s_[j][0] + s_[j][1];
            l1 += s_[j][2] + s_[j][3];
        }

        #pragma unroll
        for (int ks2 = 0; ks2 < 2; ks2++) {
            uint32_t af[4];
            af[0] = pk(s_[2 * ks2][0], s_[2 * ks2][1]);
            af[1] = pk(s_[2 * ks2][2], s_[2 * ks2][3]);
            af[2] = pk(s_[2 * ks2 + 1][0], s_[2 * ks2 + 1][1]);
            af[3] = pk(s_[2 * ks2 + 1][2], s_[2 * ks2 + 1][3]);
            #pragma unroll
            for (int tt = 0; tt < 8; tt++) {
                int r = ks2 * 16 + ((lane >> 3) & 1) * 8 + (lane & 7);
                int c = 2 * tt + (lane >> 4);
                uint32_t ad = vbase + r * 256 + ((c ^ (r & 7)) << 4);
                uint32_t b0, b1, b2, b3;
                LDM_X4T(b0, b1, b2, b3, ad);
                uint32_t bA[2] = {b0, b1}, bB[2] = {b2, b3};
                mma16(of[2 * tt], af, bA);
                mma16(of[2 * tt + 1], af, bB);
            }
        }
    }

    l0 += __shfl_xor_sync(~0u, l0, 1);
    l0 += __shfl_xor_sync(~0u, l0, 2);
    l1 += __shfl_xor_sync(~0u, l1, 1);
    l1 += __shfl_xor_sync(~0u, l1, 2);
    float il0 = 1.f / l0, il1 = 1.f / l1;
    int r0 = q0 + warp * 16 + g;
    int r1 = r0 + 8;
    #pragma unroll
    for (int j = 0; j < 16; j++) {
        int c = h * HDIM + j * 8 + 2 * tg;
        *(uint32_t*)&g_a2h[(size_t)r0 * NCAT + c] = pk(of[j][0] * il0, of[j][1] * il0);
        *(uint32_t*)&g_a2h[(size_t)r1 * NCAT + c] = pk(of[j][2] * il1, of[j][3] * il1);
    }
}

// ---------------- launch ----------------
extern "C" void kernel_launch(void* const* d_in, const int* in_sizes, int n_in,
                              void* d_out, int out_size) {
    const float* x     = (const float*)d_in[0];
    const float* vec   = (const float*)d_in[1];
    const float* pe    = (const float*)d_in[2];
    const float* w1    = (const float*)d_in[3];
    const float* b1    = (const float*)d_in[4];
    const float* w2    = (const float*)d_in[5];
    const float* b2    = (const float*)d_in[6];
    const float* mod_w = (const float*)d_in[7];
    const float* mod_b = (const float*)d_in[8];
    const float* qw    = (const float*)d_in[9];
    const float* kw    = (const float*)d_in[10];
    float* out = (float*)d_out;

    __half* w1h;  cudaGetSymbolAddress((void**)&w1h, g_w1h);
    __half* w2h;  cudaGetSymbolAddress((void**)&w2h, g_w2h);

    cudaFuncSetAttribute(gemm_cp<0>, cudaFuncAttributeMaxDynamicSharedMemorySize, 5 * 13312);
    cudaFuncSetAttribute(gemm_cp<1>, cudaFuncAttributeMaxDynamicSharedMemorySize, 5 * 13312);

    k_pre<<<36 + (HIDDEN * (N1 / 4)) / 256, 256>>>(w1, w1h, vec, mod_w, mod_b);
    k_ln<<<LSEQ, 256>>>(x);
    gemm_cp<0><<<dim3(32, 168), 128, 5 * 13312>>>(w1h, b1, nullptr, nullptr);
    k_qkrope<<<LSEQ, 256>>>(pe, qw, kw);
    k_attn<<<dim3(64, 24), 128>>>(w2, w2h);
    gemm_cp<1><<<dim3(32, 24), 128, 5 * 13312>>>(w2h, b2, out, x);
}